// round 13
// baseline (speedup 1.0000x reference)
#include <cuda_runtime.h>
#include <cuda_bf16.h>

// V[b,n,f,t] = sum_p cos(obs[b,p,f,t] - tpd[b,p,n,f])
// 4-mic square degeneracy: pairs[3]==pairs[2], pairs[5]==-pairs[0] ->
// rank-8 contraction over 4 distinct phase groups (rep pairs 0,1,2,4):
//   V = uc0*c0 + us0*s0 + uc1*c1 + us1*s1 + uc2*c2 + us2*s2 + uc3*c3 + us3*s3
//
// Round-13 = Round-12 (one block per (b,f), 160 thr, t-pair, all 36 n per
// thread) with critical-path cuts:
//  (1) obs LDGs issued at kernel top, overlapping phase-1 sincos + barrier
//  (2) three clean 12-iter inner loops (no per-iter pointer select)
//  (3) streaming stores (__stcs)

#define NP    6
#define NG    4
#define NDIR  36
#define NF    257
#define NT    300
#define NB    4
#define NTP   150          // t-pairs

__global__ __launch_bounds__(160)
void dirfeat_kernel(const float* __restrict__ obs,     // (B*P, F, T)
                    const float* __restrict__ azi,     // (B, N)
                    const float* __restrict__ ele,     // (B, N)
                    const float* __restrict__ pairs,   // (P, 3)
                    const float* __restrict__ freq,    // (F,)
                    float* __restrict__ out)           // (B, N, F, T)
{
    const int b  = blockIdx.x / NF;
    const int f  = blockIdx.x - b * NF;
    const int tid = threadIdx.x;

    // ---- Prefetch obs (issued before the phase-1 dependency chain) ----
    float2 o0, o1, o2, o3, o4, o5;
    if (tid < NTP) {
        const unsigned pstr = NF * NT;                 // 77100
        const float* ob = obs + (unsigned)((b * NP) * NF + f) * NT + tid * 2;
        o0 = *reinterpret_cast<const float2*>(ob);
        o1 = *reinterpret_cast<const float2*>(ob + 1 * pstr);
        o2 = *reinterpret_cast<const float2*>(ob + 2 * pstr);
        o3 = *reinterpret_cast<const float2*>(ob + 3 * pstr);
        o4 = *reinterpret_cast<const float2*>(ob + 4 * pstr);
        o5 = *reinterpret_cast<const float2*>(ob + 5 * pstr);
    }

    // cs[n] = {c0,s0,c1,s1, c2,s2,c3,s3}
    __shared__ __align__(16) float cs[NDIR][2 * NG];

    // ---- Phase 1: 144 steering entries, one per thread ----
    if (tid < NDIR * NG) {
        const int n = tid >> 2;
        const int g = tid & 3;
        const int rep = (g == 3) ? 4 : g;   // rep pair indices {0,1,2,4}

        const float a  = azi[b * NDIR + n];
        const float el = ele[b * NDIR + n];
        float sa, ca, se, ce;
        __sincosf(a,  &sa, &ca);
        __sincosf(el, &se, &ce);
        const float rx = se * ca, ry = se * sa, rz = ce;
        const float dot = pairs[rep * 3 + 0] * rx
                        + pairs[rep * 3 + 1] * ry
                        + pairs[rep * 3 + 2] * rz;
        const float tau = (6.283185307179586f / 343.0f) * dot * freq[f];
        float s, c;
        __sincosf(tau, &s, &c);
        cs[n][2 * g]     = c;
        cs[n][2 * g + 1] = s;
    }
    __syncthreads();

    // ---- Phase 2: threads 0..149 -> t-pair; all 36 n per thread ----
    if (tid < NTP) {
        // Combined obs terms (16 registers)
        float uc0x, uc0y, us0x, us0y;
        float uc1x, uc1y, us1x, us1y;
        float uc2x, uc2y, us2x, us2y;
        float uc3x, uc3y, us3x, us3y;

        {   // group 0: pairs 0 and 5 (negated vector -> sin difference)
            float sA, cA, sB, cB;
            __sincosf(o0.x, &sA, &cA); __sincosf(o5.x, &sB, &cB);
            uc0x = cA + cB; us0x = sA - sB;
            __sincosf(o0.y, &sA, &cA); __sincosf(o5.y, &sB, &cB);
            uc0y = cA + cB; us0y = sA - sB;
        }
        {   // group 2: pairs 2 and 3 (identical vector -> sum)
            float sA, cA, sB, cB;
            __sincosf(o2.x, &sA, &cA); __sincosf(o3.x, &sB, &cB);
            uc2x = cA + cB; us2x = sA + sB;
            __sincosf(o2.y, &sA, &cA); __sincosf(o3.y, &sB, &cB);
            uc2y = cA + cB; us2y = sA + sB;
        }
        // group 1: pair 1 alone
        __sincosf(o1.x, &us1x, &uc1x);
        __sincosf(o1.y, &us1y, &uc1y);
        // group 3: pair 4 alone
        __sincosf(o4.x, &us3x, &uc3x);
        __sincosf(o4.y, &us3y, &uc3y);

        const unsigned nstride = NF * NT;
        float* outA = out + (unsigned)((b * NDIR) * NF + f) * NT + tid * 2;
        float* outB = outA + 12u * nstride;
        float* outC = outA + 24u * nstride;
        const float4* cp = reinterpret_cast<const float4*>(&cs[0][0]);

#define DO_N(W0, W1, DST)                                              \
        {                                                              \
            const float4 w0 = (W0);                                    \
            const float4 w1 = (W1);                                    \
            float a0 = uc0x * w0.x;                                    \
            float a1 = uc0y * w0.x;                                    \
            a0 = fmaf(us0x, w0.y, a0);  a1 = fmaf(us0y, w0.y, a1);     \
            a0 = fmaf(uc1x, w0.z, a0);  a1 = fmaf(uc1y, w0.z, a1);     \
            a0 = fmaf(us1x, w0.w, a0);  a1 = fmaf(us1y, w0.w, a1);     \
            a0 = fmaf(uc2x, w1.x, a0);  a1 = fmaf(uc2y, w1.x, a1);     \
            a0 = fmaf(us2x, w1.y, a0);  a1 = fmaf(us2y, w1.y, a1);     \
            a0 = fmaf(uc3x, w1.z, a0);  a1 = fmaf(uc3y, w1.z, a1);     \
            a0 = fmaf(us3x, w1.w, a0);  a1 = fmaf(us3y, w1.w, a1);     \
            __stcs(reinterpret_cast<float2*>(DST), make_float2(a0, a1)); \
        }

#pragma unroll
        for (int i = 0; i < 12; i++)
            DO_N(cp[2 * i],      cp[2 * i + 1],      outA + i * nstride);
#pragma unroll
        for (int i = 0; i < 12; i++)
            DO_N(cp[2 * i + 24], cp[2 * i + 25],     outB + i * nstride);
#pragma unroll
        for (int i = 0; i < 12; i++)
            DO_N(cp[2 * i + 48], cp[2 * i + 49],     outC + i * nstride);
#undef DO_N
    }
}

extern "C" void kernel_launch(void* const* d_in, const int* in_sizes, int n_in,
                              void* d_out, int out_size) {
    const float* obs   = (const float*)d_in[0];
    const float* azi   = (const float*)d_in[1];
    const float* ele   = (const float*)d_in[2];
    const float* pairs = (const float*)d_in[3];
    const float* freq  = (const float*)d_in[4];
    float* out = (float*)d_out;

    dim3 grid(NB * NF);   // 1028 blocks: one per (b,f)
    dim3 block(160);      // 5 warps, 150 active in phase 2
    dirfeat_kernel<<<grid, block>>>(obs, azi, ele, pairs, freq, out);
}

// round 14
// speedup vs baseline: 1.0570x; 1.0570x over previous
#include <cuda_runtime.h>
#include <cuda_bf16.h>

// V[b,n,f,t] = sum_p cos(obs[b,p,f,t] - tpd[b,p,n,f])
// 4-mic square degeneracy: pairs[3]==pairs[2], pairs[5]==-pairs[0] ->
// rank-8 contraction over 4 distinct phase groups (rep pairs 0,1,2,4):
//   V = uc0*c0 + us0*s0 + uc1*c1 + us1*s1 + uc2*c2 + us2*s2 + uc3*c3 + us3*s3
//
// Round-14 = Round-13 with ONE change: all __sincosf replaced by
// __sinf/__cosf (guaranteed 1 MUFU each via sin.approx/cos.approx) to
// eliminate any hidden library expansion of sincos. Everything else
// (prefetch, 3x12 inner loops, __stcs streaming stores) identical.

#define NP    6
#define NG    4
#define NDIR  36
#define NF    257
#define NT    300
#define NB    4
#define NTP   150          // t-pairs

__global__ __launch_bounds__(160)
void dirfeat_kernel(const float* __restrict__ obs,     // (B*P, F, T)
                    const float* __restrict__ azi,     // (B, N)
                    const float* __restrict__ ele,     // (B, N)
                    const float* __restrict__ pairs,   // (P, 3)
                    const float* __restrict__ freq,    // (F,)
                    float* __restrict__ out)           // (B, N, F, T)
{
    const int b  = blockIdx.x / NF;
    const int f  = blockIdx.x - b * NF;
    const int tid = threadIdx.x;

    // ---- Prefetch obs (issued before the phase-1 dependency chain) ----
    float2 o0, o1, o2, o3, o4, o5;
    if (tid < NTP) {
        const unsigned pstr = NF * NT;                 // 77100
        const float* ob = obs + (unsigned)((b * NP) * NF + f) * NT + tid * 2;
        o0 = *reinterpret_cast<const float2*>(ob);
        o1 = *reinterpret_cast<const float2*>(ob + 1 * pstr);
        o2 = *reinterpret_cast<const float2*>(ob + 2 * pstr);
        o3 = *reinterpret_cast<const float2*>(ob + 3 * pstr);
        o4 = *reinterpret_cast<const float2*>(ob + 4 * pstr);
        o5 = *reinterpret_cast<const float2*>(ob + 5 * pstr);
    }

    // cs[n] = {c0,s0,c1,s1, c2,s2,c3,s3}
    __shared__ __align__(16) float cs[NDIR][2 * NG];

    // ---- Phase 1: 144 steering entries, one per thread ----
    if (tid < NDIR * NG) {
        const int n = tid >> 2;
        const int g = tid & 3;
        const int rep = (g == 3) ? 4 : g;   // rep pair indices {0,1,2,4}

        const float a  = azi[b * NDIR + n];
        const float el = ele[b * NDIR + n];
        const float sa = __sinf(a),  ca = __cosf(a);
        const float se = __sinf(el), ce = __cosf(el);
        const float rx = se * ca, ry = se * sa, rz = ce;
        const float dot = pairs[rep * 3 + 0] * rx
                        + pairs[rep * 3 + 1] * ry
                        + pairs[rep * 3 + 2] * rz;
        const float tau = (6.283185307179586f / 343.0f) * dot * freq[f];
        cs[n][2 * g]     = __cosf(tau);
        cs[n][2 * g + 1] = __sinf(tau);
    }
    __syncthreads();

    // ---- Phase 2: threads 0..149 -> t-pair; all 36 n per thread ----
    if (tid < NTP) {
        // Combined obs terms (16 registers); 24 MUFU total, 2 per element
        const float c0x = __cosf(o0.x), s0x = __sinf(o0.x);
        const float c0y = __cosf(o0.y), s0y = __sinf(o0.y);
        const float c5x = __cosf(o5.x), s5x = __sinf(o5.x);
        const float c5y = __cosf(o5.y), s5y = __sinf(o5.y);
        const float c2x = __cosf(o2.x), s2x = __sinf(o2.x);
        const float c2y = __cosf(o2.y), s2y = __sinf(o2.y);
        const float c3x = __cosf(o3.x), s3x = __sinf(o3.x);
        const float c3y = __cosf(o3.y), s3y = __sinf(o3.y);

        const float uc0x = c0x + c5x, us0x = s0x - s5x;
        const float uc0y = c0y + c5y, us0y = s0y - s5y;
        const float uc2x = c2x + c3x, us2x = s2x + s3x;
        const float uc2y = c2y + c3y, us2y = s2y + s3y;

        const float uc1x = __cosf(o1.x), us1x = __sinf(o1.x);
        const float uc1y = __cosf(o1.y), us1y = __sinf(o1.y);
        const float uc3x = __cosf(o4.x), us3x = __sinf(o4.x);
        const float uc3y = __cosf(o4.y), us3y = __sinf(o4.y);

        const unsigned nstride = NF * NT;
        float* outA = out + (unsigned)((b * NDIR) * NF + f) * NT + tid * 2;
        float* outB = outA + 12u * nstride;
        float* outC = outA + 24u * nstride;
        const float4* cp = reinterpret_cast<const float4*>(&cs[0][0]);

#define DO_N(W0, W1, DST)                                              \
        {                                                              \
            const float4 w0 = (W0);                                    \
            const float4 w1 = (W1);                                    \
            float a0 = uc0x * w0.x;                                    \
            float a1 = uc0y * w0.x;                                    \
            a0 = fmaf(us0x, w0.y, a0);  a1 = fmaf(us0y, w0.y, a1);     \
            a0 = fmaf(uc1x, w0.z, a0);  a1 = fmaf(uc1y, w0.z, a1);     \
            a0 = fmaf(us1x, w0.w, a0);  a1 = fmaf(us1y, w0.w, a1);     \
            a0 = fmaf(uc2x, w1.x, a0);  a1 = fmaf(uc2y, w1.x, a1);     \
            a0 = fmaf(us2x, w1.y, a0);  a1 = fmaf(us2y, w1.y, a1);     \
            a0 = fmaf(uc3x, w1.z, a0);  a1 = fmaf(uc3y, w1.z, a1);     \
            a0 = fmaf(us3x, w1.w, a0);  a1 = fmaf(us3y, w1.w, a1);     \
            __stcs(reinterpret_cast<float2*>(DST), make_float2(a0, a1)); \
        }

#pragma unroll
        for (int i = 0; i < 12; i++)
            DO_N(cp[2 * i],      cp[2 * i + 1],      outA + i * nstride);
#pragma unroll
        for (int i = 0; i < 12; i++)
            DO_N(cp[2 * i + 24], cp[2 * i + 25],     outB + i * nstride);
#pragma unroll
        for (int i = 0; i < 12; i++)
            DO_N(cp[2 * i + 48], cp[2 * i + 49],     outC + i * nstride);
#undef DO_N
    }
}

extern "C" void kernel_launch(void* const* d_in, const int* in_sizes, int n_in,
                              void* d_out, int out_size) {
    const float* obs   = (const float*)d_in[0];
    const float* azi   = (const float*)d_in[1];
    const float* ele   = (const float*)d_in[2];
    const float* pairs = (const float*)d_in[3];
    const float* freq  = (const float*)d_in[4];
    float* out = (float*)d_out;

    dim3 grid(NB * NF);   // 1028 blocks: one per (b,f)
    dim3 block(160);      // 5 warps, 150 active in phase 2
    dirfeat_kernel<<<grid, block>>>(obs, azi, ele, pairs, freq, out);
}